// round 6
// baseline (speedup 1.0000x reference)
#include <cuda_runtime.h>

#define HH 256
#define WW 256
#define KTOP 10
#define RADIUS 0.015f
#define RR2 (RADIUS * RADIUS)
#define EPSD 1e-4f
#define NP 20000

#define TSH 3                 // log2(tile side): 8x8 pixel tiles
#define TSIDE 8
#define TGX (WW / TSIDE)      // 32 tiles per dim
#define NTILES (TGX * TGX)    // 1024
#define CAP 256               // entries per tile (central tiles ~105)

typedef unsigned long long u64;
typedef unsigned int u32;

// ---------------- scratch (no allocations allowed) ----------------
__device__ int    g_count[NTILES];          // zero-init; re-zeroed by k_render
__device__ float4 g_bin[NTILES * CAP];      // {x_ndc, y_ndc, z, idx-as-float}

// -------------------------------------------------------------------
// Fused projection + tile binning.
__global__ void __launch_bounds__(64) k_bin(const float* __restrict__ pts,
                                            const float* __restrict__ Rm,
                                            const float* __restrict__ Tv,
                                            const float* __restrict__ focal,
                                            const float* __restrict__ pp) {
    int p = blockIdx.x * blockDim.x + threadIdx.x;
    if (p >= NP) return;
    float px = pts[3 * p + 0];
    float py = pts[3 * p + 1];
    float pz = pts[3 * p + 2];
    // pc = points @ R + T (row-vector * matrix): pc_j = sum_i p_i * R[i][j]
    float cx = fmaf(px, __ldg(Rm + 0), fmaf(py, __ldg(Rm + 3), fmaf(pz, __ldg(Rm + 6), __ldg(Tv + 0))));
    float cy = fmaf(px, __ldg(Rm + 1), fmaf(py, __ldg(Rm + 4), fmaf(pz, __ldg(Rm + 7), __ldg(Tv + 1))));
    float cz = fmaf(px, __ldg(Rm + 2), fmaf(py, __ldg(Rm + 5), fmaf(pz, __ldg(Rm + 8), __ldg(Tv + 2))));
    if (cz <= 0.01f) return;
    float iz = 1.0f / cz;
    float xn = fmaf(__ldg(focal + 0) * cx, iz, __ldg(pp + 0));
    float yn = fmaf(__ldg(focal + 1) * cy, iz, __ldg(pp + 1));

    // pixel w: xs(w) = 1 - (2w+1)/W (decreasing in w). Coverage: |xs - xn| < R.
    float wlo = (1.f - (xn + RADIUS)) * (WW * 0.5f) - 0.5f;
    float whi = (1.f - (xn - RADIUS)) * (WW * 0.5f) - 0.5f;
    int wmin = (int)floorf(wlo);
    int wmax = (int)ceilf(whi);
    float hlo = (1.f - (yn + RADIUS)) * (HH * 0.5f) - 0.5f;
    float hhi = (1.f - (yn - RADIUS)) * (HH * 0.5f) - 0.5f;
    int hmin = (int)floorf(hlo);
    int hmax = (int)ceilf(hhi);
    if (wmax < 0 || wmin > WW - 1 || hmax < 0 || hmin > HH - 1) return;
    wmin = max(wmin, 0); wmax = min(wmax, WW - 1);
    hmin = max(hmin, 0); hmax = min(hmax, HH - 1);
    int tx0 = wmin >> TSH, tx1 = wmax >> TSH;
    int ty0 = hmin >> TSH, ty1 = hmax >> TSH;

    float4 e = make_float4(xn, yn, cz, __int_as_float(p));
    for (int ty = ty0; ty <= ty1; ty++)
        for (int tx = tx0; tx <= tx1; tx++) {
            int tile = ty * TGX + tx;
            int pos = atomicAdd(&g_count[tile], 1);
            if (pos < CAP) g_bin[tile * CAP + pos] = e;
        }
}

// -------------------------------------------------------------------
// One 64-thread block per 8x8 tile; one thread per pixel.
// Single packed 64-bit key sort: (z_bits<<23)|(idx<<8)|slot — ascending order
// is exactly (z, point-idx) lexicographic (slot bits unique, never decide).
__global__ void __launch_bounds__(64) k_render(const float* __restrict__ feats,
                                               float* __restrict__ out) {
    int tile = blockIdx.x;
    int txi = tile & (TGX - 1), tyi = tile >> 5;
    int t = threadIdx.x;
    int w = txi * TSIDE + (t & (TSIDE - 1));
    int h = tyi * TSIDE + (t >> TSH);
    int pix = h * WW + w;

    int n = min(g_count[tile], CAP);
    if (t == 0 && n) g_count[tile] = 0;   // re-arm for next graph replay

    if (n == 0) {                          // empty tile fast path (image border)
        out[pix * 3 + 0] = 0.f;
        out[pix * 3 + 1] = 0.f;
        out[pix * 3 + 2] = 0.f;
        out[HH * WW * 3 + pix] = 0.f;
        out[HH * WW * 4 + pix] = 0.f;
        return;
    }

    float xs = 1.f - (2.f * w + 1.f) * (1.f / WW);
    float ys = 1.f - (2.f * h + 1.f) * (1.f / HH);
    const float4* bin = g_bin + tile * CAP;

    __shared__ u64    skey[CAP];  // packed (z_bits, idx, slot)
    __shared__ float4 she[CAP];   // entries in sorted order
    __shared__ float4 sfe[CAP];   // features in sorted order

    unsigned m = 1;               // pad to power of two for bitonic
    while (m < (unsigned)n) m <<= 1;

    for (unsigned j = t; j < m; j += 64) {
        u64 key = ~0ull;
        if (j < (unsigned)n) {
            float4 e = bin[j];
            u32 idx = (u32)__float_as_int(e.w);           // < 32768
            key = ((u64)__float_as_uint(e.z) << 23) | ((u64)idx << 8) | j;
        }
        skey[j] = key;
    }
    __syncthreads();

    // bitonic sort, ascending, key-only
    for (unsigned ksz = 2; ksz <= m; ksz <<= 1) {
        for (unsigned jsz = ksz >> 1; jsz > 0; jsz >>= 1) {
            for (unsigned i = t; i < m; i += 64) {
                unsigned ixj = i ^ jsz;
                if (ixj > i) {
                    bool up = ((i & ksz) == 0);
                    u64 a = skey[i], b2 = skey[ixj];
                    if (up ? (a > b2) : (a < b2)) {
                        skey[i] = b2; skey[ixj] = a;
                    }
                }
            }
            __syncthreads();
        }
    }

    // gather payload + features into sorted order (single pass)
    for (int i = t; i < n; i += 64) {
        unsigned slot = (unsigned)(skey[i] & 0xFF);
        float4 e = bin[slot];                 // L1-resident
        she[i] = e;
        const float* f = feats + 3 * __float_as_int(e.w);
        sfe[i] = make_float4(f[0], f[1], f[2], 0.f);
    }
    __syncthreads();

    // streaming front-to-back composite; first KTOP hits == reference top-k.
    int cnt = 0;
    float T = 1.f, wsum = 0.f, wz = 0.f;
    float r = 0.f, g = 0.f, b = 0.f;
    for (int j0 = 0; j0 < n; j0 += 16) {
        int jend = min(j0 + 16, n);
#pragma unroll 4
        for (int j = j0; j < jend; j++) {
            float4 e = she[j];
            float dx = xs - e.x;
            float dy = ys - e.y;
            float d2 = fmaf(dx, dx, dy * dy);
            if (d2 < RR2 && cnt < KTOP) {
                float wgt = 1.f - d2 * (1.f / RR2);
                float4 f = sfe[j];
                float cw = wgt * T;
                r = fmaf(cw, f.x, r);
                g = fmaf(cw, f.y, g);
                b = fmaf(cw, f.z, b);
                wsum += wgt;
                wz = fmaf(wgt, e.z, wz);
                T *= (1.f - wgt);
                cnt++;
            }
        }
        // whole warp saturated its 10-hit budget -> rest of list can't contribute
        if (__ballot_sync(0xffffffffu, cnt >= KTOP) == 0xffffffffu) break;
    }

    out[pix * 3 + 0] = fminf(fmaxf(r, 0.f), 1.f);
    out[pix * 3 + 1] = fminf(fmaxf(g, 0.f), 1.f);
    out[pix * 3 + 2] = fminf(fmaxf(b, 0.f), 1.f);
    out[HH * WW * 3 + pix] = 1.f - T;                    // mask
    out[HH * WW * 4 + pix] = wz / fmaxf(wsum, EPSD);     // depth
}

extern "C" void kernel_launch(void* const* d_in, const int* in_sizes, int n_in,
                              void* d_out, int out_size) {
    const float* points    = (const float*)d_in[0];
    const float* features  = (const float*)d_in[1];
    const float* Rm        = (const float*)d_in[2];
    const float* Tv        = (const float*)d_in[3];
    const float* focal     = (const float*)d_in[4];
    const float* principal = (const float*)d_in[5];
    float* out = (float*)d_out;

    k_bin<<<(NP + 63) / 64, 64>>>(points, Rm, Tv, focal, principal);
    k_render<<<NTILES, 64>>>(features, out);
}

// round 8
// speedup vs baseline: 1.0707x; 1.0707x over previous
#include <cuda_runtime.h>

#define HH 256
#define WW 256
#define KTOP 10
#define RADIUS 0.015f
#define RR2 (RADIUS * RADIUS)
#define EPSD 1e-4f
#define NP 20000

#define TSH 3                 // log2(tile side): 8x8 pixel tiles
#define TSIDE 8
#define TGX (WW / TSIDE)      // 32 tiles per dim
#define NTILES (TGX * TGX)    // 1024
#define CAPB 192              // entries per tile (mean ~79, >12 sigma margin)

typedef unsigned long long u64;
typedef unsigned int u32;

// ---------------- scratch (no allocations allowed) ----------------
__device__ int    g_count[NTILES];          // zero-init; re-zeroed by k_render
__device__ float4 g_bin[NTILES * CAPB];     // {x_ndc, y_ndc, z, idx-as-float}

// -------------------------------------------------------------------
// Fused projection + tile binning.
__global__ void __launch_bounds__(64) k_bin(const float* __restrict__ pts,
                                            const float* __restrict__ Rm,
                                            const float* __restrict__ Tv,
                                            const float* __restrict__ focal,
                                            const float* __restrict__ pp) {
    int p = blockIdx.x * blockDim.x + threadIdx.x;
    if (p >= NP) return;
    float px = pts[3 * p + 0];
    float py = pts[3 * p + 1];
    float pz = pts[3 * p + 2];
    // pc = points @ R + T (row-vector * matrix): pc_j = sum_i p_i * R[i][j]
    float cx = fmaf(px, __ldg(Rm + 0), fmaf(py, __ldg(Rm + 3), fmaf(pz, __ldg(Rm + 6), __ldg(Tv + 0))));
    float cy = fmaf(px, __ldg(Rm + 1), fmaf(py, __ldg(Rm + 4), fmaf(pz, __ldg(Rm + 7), __ldg(Tv + 1))));
    float cz = fmaf(px, __ldg(Rm + 2), fmaf(py, __ldg(Rm + 5), fmaf(pz, __ldg(Rm + 8), __ldg(Tv + 2))));
    if (cz <= 0.01f) return;
    float iz = 1.0f / cz;
    float xn = fmaf(__ldg(focal + 0) * cx, iz, __ldg(pp + 0));
    float yn = fmaf(__ldg(focal + 1) * cy, iz, __ldg(pp + 1));

    // pixel w: xs(w) = 1 - (2w+1)/W (decreasing in w). Coverage: |xs - xn| < R.
    float wlo = (1.f - (xn + RADIUS)) * (WW * 0.5f) - 0.5f;
    float whi = (1.f - (xn - RADIUS)) * (WW * 0.5f) - 0.5f;
    int wmin = (int)floorf(wlo);
    int wmax = (int)ceilf(whi);
    float hlo = (1.f - (yn + RADIUS)) * (HH * 0.5f) - 0.5f;
    float hhi = (1.f - (yn - RADIUS)) * (HH * 0.5f) - 0.5f;
    int hmin = (int)floorf(hlo);
    int hmax = (int)ceilf(hhi);
    if (wmax < 0 || wmin > WW - 1 || hmax < 0 || hmin > HH - 1) return;
    wmin = max(wmin, 0); wmax = min(wmax, WW - 1);
    hmin = max(hmin, 0); hmax = min(hmax, HH - 1);
    int tx0 = wmin >> TSH, tx1 = wmax >> TSH;
    int ty0 = hmin >> TSH, ty1 = hmax >> TSH;

    float4 e = make_float4(xn, yn, cz, __int_as_float(p));
    for (int ty = ty0; ty <= ty1; ty++)
        for (int tx = tx0; tx <= tx1; tx++) {
            int tile = ty * TGX + tx;
            int pos = atomicAdd(&g_count[tile], 1);
            if (pos < CAPB) g_bin[tile * CAPB + pos] = e;
        }
}

// -------------------------------------------------------------------
// One 64-thread block per 8x8 tile; one thread per pixel.
// Packed key: (z_bits<<23)|(idx<<8)|slot — ascending == (z, point-idx) order.
// Warp-local bitonic: warp w owns contiguous half; only jsz==m/2 crosses.
__global__ void __launch_bounds__(64) k_render(const float* __restrict__ feats,
                                               float* __restrict__ out) {
    int tile = blockIdx.x;
    int txi = tile & (TGX - 1), tyi = tile >> 5;
    int t = threadIdx.x;
    int lane = t & 31, wid = t >> 5;
    int w = txi * TSIDE + (t & (TSIDE - 1));
    int h = tyi * TSIDE + (t >> TSH);
    int pix = h * WW + w;

    int n = min(g_count[tile], CAPB);
    if (t == 0 && n) g_count[tile] = 0;   // re-arm for next graph replay

    if (n == 0) {                          // empty tile fast path (image border)
        out[pix * 3 + 0] = 0.f;
        out[pix * 3 + 1] = 0.f;
        out[pix * 3 + 2] = 0.f;
        out[HH * WW * 3 + pix] = 0.f;
        out[HH * WW * 4 + pix] = 0.f;
        return;
    }

    float xs = 1.f - (2.f * w + 1.f) * (1.f / WW);
    float ys = 1.f - (2.f * h + 1.f) * (1.f / HH);
    const float4* bin = g_bin + tile * CAPB;

    __shared__ u64    skey[256];   // packed (z, idx, slot); padded to m
    __shared__ float4 sh[CAPB];    // entry payload, load order
    __shared__ float4 sf[CAPB];    // feature rgb,   load order
    __shared__ float4 she[CAPB];   // entries in sorted order
    __shared__ float4 sfe[CAPB];   // features in sorted order

    unsigned m = (n <= 128) ? 128u : 256u;

    // stage payload + build keys + prefetch features (LDG latency overlaps sort)
    for (unsigned j = t; j < m; j += 64) {
        u64 key = ~0ull;
        if (j < (unsigned)n) {
            float4 e = bin[j];
            sh[j] = e;
            int idx = __float_as_int(e.w);                // < 32768
            key = ((u64)__float_as_uint(e.z) << 23) | ((u64)(u32)idx << 8) | j;
            const float* f = feats + 3 * idx;
            sf[j] = make_float4(f[0], f[1], f[2], 0.f);
        }
        skey[j] = key;
    }

    // bitonic sort, ascending. Warp wid owns [wid*half, wid*half+half).
    // Compare distance jsz crosses halves only when jsz == half.
    unsigned half = m >> 1;
    unsigned base = (unsigned)wid * half;
    bool carry = true;                     // first phase: full barrier (key build)
    for (unsigned ksz = 2; ksz <= m; ksz <<= 1) {
        for (unsigned jsz = ksz >> 1; jsz > 0; jsz >>= 1) {
            bool cross = (jsz >= half);
            if (cross || carry) __syncthreads(); else __syncwarp();
            carry = cross;
            for (unsigned i = base + lane; i < base + half; i += 32) {
                unsigned ixj = i ^ jsz;
                if (ixj > i) {
                    bool up = ((i & ksz) == 0);
                    u64 a = skey[i], b2 = skey[ixj];
                    if (up ? (a > b2) : (a < b2)) {
                        skey[i] = b2; skey[ixj] = a;
                    }
                }
            }
        }
    }
    __syncthreads();

    // permute payload + features into sorted order (smem -> smem)
    for (int i = t; i < n; i += 64) {
        unsigned slot = (unsigned)(skey[i] & 0xFF);
        she[i] = sh[slot];
        sfe[i] = sf[slot];
    }
    __syncthreads();

    // streaming front-to-back composite; first KTOP hits == reference top-k
    // (z-ascending with lowest-idx tie-break), running T == cumprod.
    int cnt = 0;
    float T = 1.f, wsum = 0.f, wz = 0.f;
    float r = 0.f, g = 0.f, b = 0.f;
#pragma unroll 4
    for (int j = 0; j < n; j++) {
        float4 e = she[j];
        float dx = xs - e.x;
        float dy = ys - e.y;
        float d2 = fmaf(dx, dx, dy * dy);
        if (d2 < RR2 && cnt < KTOP) {
            float wgt = 1.f - d2 * (1.f / RR2);
            float4 f = sfe[j];
            float cw = wgt * T;
            r = fmaf(cw, f.x, r);
            g = fmaf(cw, f.y, g);
            b = fmaf(cw, f.z, b);
            wsum += wgt;
            wz = fmaf(wgt, e.z, wz);
            T *= (1.f - wgt);
            cnt++;
        }
    }

    out[pix * 3 + 0] = fminf(fmaxf(r, 0.f), 1.f);
    out[pix * 3 + 1] = fminf(fmaxf(g, 0.f), 1.f);
    out[pix * 3 + 2] = fminf(fmaxf(b, 0.f), 1.f);
    out[HH * WW * 3 + pix] = 1.f - T;                    // mask
    out[HH * WW * 4 + pix] = wz / fmaxf(wsum, EPSD);     // depth
}

extern "C" void kernel_launch(void* const* d_in, const int* in_sizes, int n_in,
                              void* d_out, int out_size) {
    const float* points    = (const float*)d_in[0];
    const float* features  = (const float*)d_in[1];
    const float* Rm        = (const float*)d_in[2];
    const float* Tv        = (const float*)d_in[3];
    const float* focal     = (const float*)d_in[4];
    const float* principal = (const float*)d_in[5];
    float* out = (float*)d_out;

    k_bin<<<(NP + 63) / 64, 64>>>(points, Rm, Tv, focal, principal);
    k_render<<<NTILES, 64>>>(features, out);
}

// round 9
// speedup vs baseline: 1.2975x; 1.2118x over previous
#include <cuda_runtime.h>

#define HH 256
#define WW 256
#define KTOP 10
#define RADIUS 0.015f
#define RR2 (RADIUS * RADIUS)
#define EPSD 1e-4f
#define NP 20000

// 8x4 pixel tiles, one warp per tile
#define TSHX 3
#define TSHY 2
#define TGX (WW >> TSHX)      // 32 tiles in x
#define TGY (HH >> TSHY)      // 64 tiles in y
#define NTILES (TGX * TGY)    // 2048
#define CAP 128               // entries per tile (mean ~44, +12 sigma)

typedef unsigned long long u64;
typedef unsigned int u32;

// ---------------- scratch (no allocations allowed) ----------------
__device__ int    g_count[NTILES];          // zero-init; re-zeroed by k_render
__device__ float4 g_bin[NTILES * CAP];      // {x_ndc, y_ndc, z, idx-as-float}

// -------------------------------------------------------------------
// Fused projection + tile binning.
__global__ void __launch_bounds__(64) k_bin(const float* __restrict__ pts,
                                            const float* __restrict__ Rm,
                                            const float* __restrict__ Tv,
                                            const float* __restrict__ focal,
                                            const float* __restrict__ pp) {
    int p = blockIdx.x * blockDim.x + threadIdx.x;
    if (p >= NP) return;
    float px = pts[3 * p + 0];
    float py = pts[3 * p + 1];
    float pz = pts[3 * p + 2];
    // pc = points @ R + T (row-vector * matrix): pc_j = sum_i p_i * R[i][j]
    float cx = fmaf(px, __ldg(Rm + 0), fmaf(py, __ldg(Rm + 3), fmaf(pz, __ldg(Rm + 6), __ldg(Tv + 0))));
    float cy = fmaf(px, __ldg(Rm + 1), fmaf(py, __ldg(Rm + 4), fmaf(pz, __ldg(Rm + 7), __ldg(Tv + 1))));
    float cz = fmaf(px, __ldg(Rm + 2), fmaf(py, __ldg(Rm + 5), fmaf(pz, __ldg(Rm + 8), __ldg(Tv + 2))));
    if (cz <= 0.01f) return;
    float iz = 1.0f / cz;
    float xn = fmaf(__ldg(focal + 0) * cx, iz, __ldg(pp + 0));
    float yn = fmaf(__ldg(focal + 1) * cy, iz, __ldg(pp + 1));

    // pixel w: xs(w) = 1 - (2w+1)/W (decreasing in w). Coverage: |xs - xn| < R.
    float wlo = (1.f - (xn + RADIUS)) * (WW * 0.5f) - 0.5f;
    float whi = (1.f - (xn - RADIUS)) * (WW * 0.5f) - 0.5f;
    int wmin = (int)floorf(wlo);
    int wmax = (int)ceilf(whi);
    float hlo = (1.f - (yn + RADIUS)) * (HH * 0.5f) - 0.5f;
    float hhi = (1.f - (yn - RADIUS)) * (HH * 0.5f) - 0.5f;
    int hmin = (int)floorf(hlo);
    int hmax = (int)ceilf(hhi);
    if (wmax < 0 || wmin > WW - 1 || hmax < 0 || hmin > HH - 1) return;
    wmin = max(wmin, 0); wmax = min(wmax, WW - 1);
    hmin = max(hmin, 0); hmax = min(hmax, HH - 1);
    int tx0 = wmin >> TSHX, tx1 = wmax >> TSHX;
    int ty0 = hmin >> TSHY, ty1 = hmax >> TSHY;

    float4 e = make_float4(xn, yn, cz, __int_as_float(p));
    for (int ty = ty0; ty <= ty1; ty++)
        for (int tx = tx0; tx <= tx1; tx++) {
            int tile = ty * TGX + tx;
            int pos = atomicAdd(&g_count[tile], 1);
            if (pos < CAP) g_bin[tile * CAP + pos] = e;
        }
}

// -------------------------------------------------------------------
__device__ __forceinline__ u64 shfl_xor_u64(u64 v, int m) {
    u32 lo = (u32)v, hi = (u32)(v >> 32);
    lo = __shfl_xor_sync(0xffffffffu, lo, m);
    hi = __shfl_xor_sync(0xffffffffu, hi, m);
    return ((u64)hi << 32) | lo;
}

// In-register warp bitonic sort of NK*32 u64 keys, ascending.
// Element index i = k*32 + lane. Keys unique (slot bits), so ties can't occur.
template <int NK>
__device__ __forceinline__ void bitonic_warp(u64* V, int lane) {
    const int M = NK * 32;
#pragma unroll
    for (int ksz = 2; ksz <= M; ksz <<= 1) {
#pragma unroll
        for (int jsz = ksz >> 1; jsz > 0; jsz >>= 1) {
            if (jsz >= 32) {
                int j32 = jsz >> 5;
#pragma unroll
                for (int k = 0; k < NK; k++) {
                    if ((k & j32) == 0) {
                        int kb = k | j32;
                        bool up = (((k * 32) & ksz) == 0);   // ksz>=64 here
                        u64 a = V[k], b = V[kb];
                        if ((a > b) == up) { V[k] = b; V[kb] = a; }
                    }
                }
            } else {
#pragma unroll
                for (int k = 0; k < NK; k++) {
                    u64 p = shfl_xor_u64(V[k], jsz);
                    bool up = (((k * 32 + lane) & ksz) == 0);
                    bool lower = ((lane & jsz) == 0);
                    u64 mn = (V[k] < p) ? V[k] : p;
                    u64 mx = (V[k] < p) ? p : V[k];
                    V[k] = (lower == up) ? mn : mx;
                }
            }
        }
    }
}

// -------------------------------------------------------------------
// One warp per 8x4 tile; one lane per pixel. Warp-autonomous: no block barriers.
// Packed key: (z_bits<<23)|(idx<<8)|slot — ascending == (z, point-idx) order.
__global__ void __launch_bounds__(64) k_render(const float* __restrict__ feats,
                                               float* __restrict__ out) {
    int wrp = threadIdx.x >> 5, lane = threadIdx.x & 31;
    int tile = blockIdx.x * 2 + wrp;
    int txi = tile & (TGX - 1), tyi = tile >> 5;
    int w = (txi << TSHX) + (lane & 7);
    int h = (tyi << TSHY) + (lane >> 3);
    int pix = h * WW + w;

    int n = min(g_count[tile], CAP);
    if (lane == 0 && n) g_count[tile] = 0;   // re-arm for next graph replay

    if (n == 0) {                            // empty tile fast path
        out[pix * 3 + 0] = 0.f;
        out[pix * 3 + 1] = 0.f;
        out[pix * 3 + 2] = 0.f;
        out[HH * WW * 3 + pix] = 0.f;
        out[HH * WW * 4 + pix] = 0.f;
        return;
    }

    float xs = 1.f - (2.f * w + 1.f) * (1.f / WW);
    float ys = 1.f - (2.f * h + 1.f) * (1.f / HH);
    const float4* bin = g_bin + tile * CAP;

    __shared__ float4 s_sh[2][CAP];    // payload, load order
    __shared__ float4 s_sf[2][CAP];    // feature rgb, load order
    __shared__ float4 s_she[2][CAP];   // payload, sorted order
    __shared__ float4 s_sfe[2][CAP];   // features, sorted order
    float4* SH = s_sh[wrp];
    float4* SF = s_sf[wrp];
    float4* SHE = s_she[wrp];
    float4* SFE = s_sfe[wrp];

    // stage payload + build keys in registers + prefetch features
    u64 V[4];
#pragma unroll
    for (int k = 0; k < 4; k++) {
        int j = k * 32 + lane;
        u64 key = ~0ull;
        if (j < n) {
            float4 e = bin[j];
            SH[j] = e;
            int idx = __float_as_int(e.w);                 // < 32768
            key = ((u64)__float_as_uint(e.z) << 23) | ((u64)(u32)idx << 8) | (u32)j;
            const float* f = feats + 3 * idx;
            SF[j] = make_float4(f[0], f[1], f[2], 0.f);
        }
        V[k] = key;
    }
    __syncwarp();

    int nk = (n <= 64) ? 2 : 4;
    if (nk == 2) bitonic_warp<2>(V, lane);
    else         bitonic_warp<4>(V, lane);

    // scatter payload/features into sorted order straight from register keys
#pragma unroll
    for (int k = 0; k < 4; k++) {
        int i = k * 32 + lane;
        if (k < nk && i < n) {
            unsigned slot = (unsigned)(V[k] & 0xFF);
            SHE[i] = SH[slot];
            SFE[i] = SF[slot];
        }
    }
    __syncwarp();

    // streaming front-to-back composite; first KTOP hits == reference top-k
    // (z-ascending, lowest-idx tie-break); running T == cumprod.
    int cnt = 0;
    float T = 1.f, wsum = 0.f, wz = 0.f;
    float r = 0.f, g = 0.f, b = 0.f;
#pragma unroll 4
    for (int j = 0; j < n; j++) {
        float4 e = SHE[j];
        float dx = xs - e.x;
        float dy = ys - e.y;
        float d2 = fmaf(dx, dx, dy * dy);
        if (d2 < RR2 && cnt < KTOP) {
            float wgt = 1.f - d2 * (1.f / RR2);
            float4 f = SFE[j];
            float cw = wgt * T;
            r = fmaf(cw, f.x, r);
            g = fmaf(cw, f.y, g);
            b = fmaf(cw, f.z, b);
            wsum += wgt;
            wz = fmaf(wgt, e.z, wz);
            T *= (1.f - wgt);
            cnt++;
        }
    }

    out[pix * 3 + 0] = fminf(fmaxf(r, 0.f), 1.f);
    out[pix * 3 + 1] = fminf(fmaxf(g, 0.f), 1.f);
    out[pix * 3 + 2] = fminf(fmaxf(b, 0.f), 1.f);
    out[HH * WW * 3 + pix] = 1.f - T;                    // mask
    out[HH * WW * 4 + pix] = wz / fmaxf(wsum, EPSD);     // depth
}

extern "C" void kernel_launch(void* const* d_in, const int* in_sizes, int n_in,
                              void* d_out, int out_size) {
    const float* points    = (const float*)d_in[0];
    const float* features  = (const float*)d_in[1];
    const float* Rm        = (const float*)d_in[2];
    const float* Tv        = (const float*)d_in[3];
    const float* focal     = (const float*)d_in[4];
    const float* principal = (const float*)d_in[5];
    float* out = (float*)d_out;

    k_bin<<<(NP + 63) / 64, 64>>>(points, Rm, Tv, focal, principal);
    k_render<<<NTILES / 2, 64>>>(features, out);
}